// round 1
// baseline (speedup 1.0000x reference)
#include <cuda_runtime.h>
#include <cstdint>

// out[nat, 48] = segment_sum(x*switch, src) - segment_sum(x*switch, dst)
// E = 1.6M, D = 48, nat = 50k.
// Strategy: 12 threads per edge (one float4 each), red.global.add.v4.f32
// to L2-resident output (9.6 MB << 126 MB L2).

#define D_FEAT 48
#define VECS_PER_EDGE (D_FEAT / 4)   // 12

__global__ void zero_out_kernel(float4* __restrict__ out, int n_vec) {
    int i = blockIdx.x * blockDim.x + threadIdx.x;
    if (i < n_vec) out[i] = make_float4(0.f, 0.f, 0.f, 0.f);
}

__global__ void scatter_edges_kernel(const float4* __restrict__ x4,
                                     const float* __restrict__ sw,
                                     const int* __restrict__ esrc,
                                     const int* __restrict__ edst,
                                     float* __restrict__ out,
                                     int n_edges) {
    int t = blockIdx.x * blockDim.x + threadIdx.x;
    int total = n_edges * VECS_PER_EDGE;
    if (t >= total) return;

    int e = t / VECS_PER_EDGE;
    int c = t - e * VECS_PER_EDGE;   // 0..11

    float s = sw[e];
    float4 v = x4[(size_t)e * VECS_PER_EDGE + c];
    float vx = v.x * s, vy = v.y * s, vz = v.z * s, vw = v.w * s;

    int src = esrc[e];
    int dst = edst[e];

    float* ps = out + (size_t)src * D_FEAT + c * 4;
    float* pd = out + (size_t)dst * D_FEAT + c * 4;

    asm volatile("red.global.add.v4.f32 [%0], {%1,%2,%3,%4};"
                 :: "l"(ps), "f"(vx), "f"(vy), "f"(vz), "f"(vw) : "memory");
    asm volatile("red.global.add.v4.f32 [%0], {%1,%2,%3,%4};"
                 :: "l"(pd), "f"(-vx), "f"(-vy), "f"(-vz), "f"(-vw) : "memory");
}

extern "C" void kernel_launch(void* const* d_in, const int* in_sizes, int n_in,
                              void* d_out, int out_size) {
    const float4* x4  = (const float4*)d_in[0];   // x [E, 48] fp32
    const float*  sw  = (const float*)d_in[1];    // switch [E]
    const int*    src = (const int*)d_in[2];      // edge_src [E]
    const int*    dst = (const int*)d_in[3];      // edge_dst [E]
    float*        out = (float*)d_out;            // [nat, 48] fp32

    int n_edges = in_sizes[1];                    // E from switch
    int n_out_vec = out_size / 4;                 // out_size elements / 4 per float4

    zero_out_kernel<<<(n_out_vec + 255) / 256, 256>>>((float4*)out, n_out_vec);

    int total = n_edges * VECS_PER_EDGE;
    scatter_edges_kernel<<<(total + 255) / 256, 256>>>(x4, sw, src, dst, out, n_edges);
}

// round 2
// speedup vs baseline: 1.0960x; 1.0960x over previous
#include <cuda_runtime.h>
#include <cstdint>

// out[nat, 48] = segment_sum(x*switch, src) - segment_sum(x*switch, dst)
// E = 1.6M, D = 48, nat = 50k.
// 12 threads per edge (one float4 each), 2 edges per thread for MLP,
// red.global.add.v4.f32 to L2-resident output (9.6 MB << 126 MB L2).
// x loaded with streaming hint (no reuse).

#define D_FEAT 48
#define VECS_PER_EDGE (D_FEAT / 4)   // 12

__global__ void zero_out_kernel(float4* __restrict__ out, int n_vec) {
    int i = blockIdx.x * blockDim.x + threadIdx.x;
    if (i < n_vec) out[i] = make_float4(0.f, 0.f, 0.f, 0.f);
}

__device__ __forceinline__ void red_v4(float* p, float a, float b, float c, float d) {
    asm volatile("red.global.add.v4.f32 [%0], {%1,%2,%3,%4};"
                 :: "l"(p), "f"(a), "f"(b), "f"(c), "f"(d) : "memory");
}

__global__ void __launch_bounds__(256)
scatter_edges_kernel(const float4* __restrict__ x4,
                     const float* __restrict__ sw,
                     const int* __restrict__ esrc,
                     const int* __restrict__ edst,
                     float* __restrict__ out,
                     int half_edges) {
    int t = blockIdx.x * blockDim.x + threadIdx.x;
    int total = half_edges * VECS_PER_EDGE;
    if (t >= total) return;

    int e0 = t / VECS_PER_EDGE;
    int c  = t - e0 * VECS_PER_EDGE;   // 0..11
    int e1 = e0 + half_edges;

    // Front-load everything (max MLP)
    float s0 = __ldg(sw + e0);
    float s1 = __ldg(sw + e1);
    int src0 = __ldg(esrc + e0);
    int src1 = __ldg(esrc + e1);
    int dst0 = __ldg(edst + e0);
    int dst1 = __ldg(edst + e1);
    float4 v0 = __ldcs(x4 + (size_t)e0 * VECS_PER_EDGE + c);   // streaming: no reuse
    float4 v1 = __ldcs(x4 + (size_t)e1 * VECS_PER_EDGE + c);

    float ax = v0.x * s0, ay = v0.y * s0, az = v0.z * s0, aw = v0.w * s0;
    float bx = v1.x * s1, by = v1.y * s1, bz = v1.z * s1, bw = v1.w * s1;

    size_t co = (size_t)c * 4;
    red_v4(out + (size_t)src0 * D_FEAT + co,  ax,  ay,  az,  aw);
    red_v4(out + (size_t)src1 * D_FEAT + co,  bx,  by,  bz,  bw);
    red_v4(out + (size_t)dst0 * D_FEAT + co, -ax, -ay, -az, -aw);
    red_v4(out + (size_t)dst1 * D_FEAT + co, -bx, -by, -bz, -bw);
}

extern "C" void kernel_launch(void* const* d_in, const int* in_sizes, int n_in,
                              void* d_out, int out_size) {
    const float4* x4  = (const float4*)d_in[0];   // x [E, 48] fp32
    const float*  sw  = (const float*)d_in[1];    // switch [E]
    const int*    src = (const int*)d_in[2];      // edge_src [E]
    const int*    dst = (const int*)d_in[3];      // edge_dst [E]
    float*        out = (float*)d_out;            // [nat, 48] fp32

    int n_edges = in_sizes[1];
    int half_edges = n_edges / 2;                 // E = 1.6M, even
    int n_out_vec = out_size / 4;

    zero_out_kernel<<<(n_out_vec + 255) / 256, 256>>>((float4*)out, n_out_vec);

    int total = half_edges * VECS_PER_EDGE;
    scatter_edges_kernel<<<(total + 255) / 256, 256>>>(x4, sw, src, dst, out, half_edges);
}